// round 5
// baseline (speedup 1.0000x reference)
#include <cuda_runtime.h>
#include <cuda_bf16.h>
#include <cstddef>

// Problem constants
#define B_  4
#define T_  4096
#define D_  1024
#define H_  16
#define HD_ 64
#define BT_ (B_ * T_)          // 16384 rows
#define BH_ (B_ * H_)          // 64 (b,h) pairs

// ---------------------------------------------------------------------------
// Scratch (device globals: allocation-free per harness rules).
// NOTE: attn output is aliased onto g_k (k is dead after kv_reduce), keeping
// the static footprint at 3x64MB instead of 4x64MB.
// ---------------------------------------------------------------------------
__device__ float g_q[(size_t)BT_ * D_];      // 64 MB, (B,T,D) layout
__device__ float g_k[(size_t)BT_ * D_];      // k, later reused as attn
__device__ float g_v[(size_t)BT_ * D_];
__device__ float g_kv[(size_t)BH_ * HD_ * HD_];   // (bh, d, e)
__device__ float g_ksum[(size_t)BH_ * HD_];

__device__ __forceinline__ float phi_fn(float x) {
    // elu(x)+1 : x>0 -> x+1 ; else exp(x)
    return x > 0.f ? x + 1.f : __expf(x);
}

// ---------------------------------------------------------------------------
// GEMM: C[row, col] = sum_k A[row,k] * W[col,k]   (A: M x K, W: N x K, both row-major)
// mode bit0 = apply phi, bit1 = apply mask (zero row where mask[row] != 0, AFTER phi)
// M = BT_ = 16384, N = K = D_ = 1024. Tile 128x128x8, 256 threads, 8x8 per thread.
// mask is int32 (harness marshals bool -> int32).
// ---------------------------------------------------------------------------
__global__ __launch_bounds__(256) void gemm_kernel(
    const float* __restrict__ A,
    const float* __restrict__ W,
    float* __restrict__ C,
    const int* __restrict__ mask,
    int mode)
{
    const int K = D_;
    const int N = D_;
    __shared__ float As[8][128];
    __shared__ float Bs[8][128];

    const int tid = threadIdx.x;
    const int rowBase = blockIdx.x * 128;
    const int colBase = blockIdx.y * 128;

    const int lm = tid >> 1;          // 0..127 (row within tile for loading)
    const int lk = (tid & 1) << 2;    // 0 or 4

    const int tx = tid & 15;          // col group
    const int ty = tid >> 4;          // row group

    float c[8][8];
    #pragma unroll
    for (int i = 0; i < 8; i++)
        #pragma unroll
        for (int j = 0; j < 8; j++)
            c[i][j] = 0.f;

    const float* Aptr = A + (size_t)(rowBase + lm) * K + lk;
    const float* Wptr = W + (size_t)(colBase + lm) * K + lk;

    for (int kb = 0; kb < K; kb += 8) {
        float4 a4 = *(const float4*)(Aptr + kb);
        float4 b4 = *(const float4*)(Wptr + kb);
        As[lk + 0][lm] = a4.x;
        As[lk + 1][lm] = a4.y;
        As[lk + 2][lm] = a4.z;
        As[lk + 3][lm] = a4.w;
        Bs[lk + 0][lm] = b4.x;
        Bs[lk + 1][lm] = b4.y;
        Bs[lk + 2][lm] = b4.z;
        Bs[lk + 3][lm] = b4.w;
        __syncthreads();

        #pragma unroll
        for (int kk = 0; kk < 8; kk++) {
            float a[8], bb[8];
            *(float4*)(a)      = *(const float4*)(&As[kk][ty * 8]);
            *(float4*)(a + 4)  = *(const float4*)(&As[kk][ty * 8 + 4]);
            *(float4*)(bb)     = *(const float4*)(&Bs[kk][tx * 8]);
            *(float4*)(bb + 4) = *(const float4*)(&Bs[kk][tx * 8 + 4]);
            #pragma unroll
            for (int i = 0; i < 8; i++)
                #pragma unroll
                for (int j = 0; j < 8; j++)
                    c[i][j] = fmaf(a[i], bb[j], c[i][j]);
        }
        __syncthreads();
    }

    const bool do_phi  = (mode & 1) != 0;
    const bool do_mask = (mode & 2) != 0;

    #pragma unroll
    for (int i = 0; i < 8; i++) {
        const int row = rowBase + ty * 8 + i;
        bool mz = false;
        if (do_mask) mz = (mask[row] != 0);   // mask index == b*T + t == row
        float* crow = C + (size_t)row * N + colBase + tx * 8;
        #pragma unroll
        for (int j = 0; j < 8; j++) {
            float val = c[i][j];
            if (do_phi)  val = phi_fn(val);
            if (do_mask && mz) val = 0.f;
            crow[j] = val;
        }
    }
}

// ---------------------------------------------------------------------------
// kv pooling: kv[bh][d][e] = sum_t k[b,t,h,d] * v[b,t,h,e]
//             ksum[bh][d]  = sum_t k[b,t,h,d]
// grid (BH, 4): block owns all 64 d's and 16 e-columns. 256 threads.
// ---------------------------------------------------------------------------
__global__ __launch_bounds__(256) void kv_reduce(
    const float* __restrict__ k,
    const float* __restrict__ v,
    float* __restrict__ kv,
    float* __restrict__ ksum)
{
    const int bh = blockIdx.x;
    const int jt = blockIdx.y;
    const int b  = bh >> 4;
    const int h  = bh & 15;
    const int jbase = jt * 16;

    __shared__ float ks[64][64];
    __shared__ float vs[64][16];

    const int tid = threadIdx.x;
    const int i   = tid & 63;          // d index owned
    const int jj0 = (tid >> 6) * 4;    // e sub-offset (0,4,8,12)

    float acc0 = 0.f, acc1 = 0.f, acc2 = 0.f, acc3 = 0.f, ksacc = 0.f;
    const size_t base = ((size_t)b * T_) * D_ + h * HD_;

    for (int t0 = 0; t0 < T_; t0 += 64) {
        #pragma unroll
        for (int r = 0; r < 16; r++) {
            int idx = r * 256 + tid;
            int tl = idx >> 6, ii = idx & 63;
            ks[tl][ii] = k[base + (size_t)(t0 + tl) * D_ + ii];
        }
        #pragma unroll
        for (int r = 0; r < 4; r++) {
            int idx = r * 256 + tid;
            int tl = idx >> 4, jj = idx & 15;
            vs[tl][jj] = v[base + (size_t)(t0 + tl) * D_ + jbase + jj];
        }
        __syncthreads();

        #pragma unroll 8
        for (int tl = 0; tl < 64; tl++) {
            float kk = ks[tl][i];
            ksacc += kk;                       // == per-i column sum (write-gated below)
            acc0 = fmaf(kk, vs[tl][jj0 + 0], acc0);
            acc1 = fmaf(kk, vs[tl][jj0 + 1], acc1);
            acc2 = fmaf(kk, vs[tl][jj0 + 2], acc2);
            acc3 = fmaf(kk, vs[tl][jj0 + 3], acc3);
        }
        __syncthreads();
    }

    float* kvb = kv + (size_t)bh * HD_ * HD_;
    kvb[i * HD_ + jbase + jj0 + 0] = acc0;
    kvb[i * HD_ + jbase + jj0 + 1] = acc1;
    kvb[i * HD_ + jbase + jj0 + 2] = acc2;
    kvb[i * HD_ + jbase + jj0 + 3] = acc3;
    if (jt == 0 && tid < 64)
        ksum[bh * HD_ + tid] = ksacc;
}

// ---------------------------------------------------------------------------
// apply: attn[b,t,h,e] = (sum_d q[b,t,h,d]*kv[bh][d][e]) / max(sum_d q*ksum, 1e-6)
// grid (BH, T/128). 256 threads = 4 t's per iteration, 64 lanes per t.
// attn may alias the k buffer (k is dead here).
// ---------------------------------------------------------------------------
__global__ __launch_bounds__(256) void attn_apply(
    const float* __restrict__ q,
    const float* __restrict__ kv,
    const float* __restrict__ ksum,
    float* __restrict__ attn)
{
    const int bh = blockIdx.x;
    const int b  = bh >> 4;
    const int h  = bh & 15;
    const int tbase = blockIdx.y * 128;

    __shared__ float kvs[64][64];
    __shared__ float kss[64];
    __shared__ float qs[4][64];

    const int tid = threadIdx.x;
    const float* kvb = kv + (size_t)bh * HD_ * HD_;
    #pragma unroll
    for (int r = 0; r < 16; r++) {
        int idx = r * 256 + tid;
        kvs[idx >> 6][idx & 63] = kvb[idx];
    }
    if (tid < 64) kss[tid] = ksum[bh * HD_ + tid];
    __syncthreads();

    const int g = tid >> 6, lane = tid & 63;
    const size_t base = ((size_t)b * T_) * D_ + h * HD_;

    for (int t0 = tbase; t0 < tbase + 128; t0 += 4) {
        const int t = t0 + g;
        qs[g][lane] = q[base + (size_t)t * D_ + lane];
        __syncthreads();
        float o = 0.f, nrm = 0.f;
        #pragma unroll
        for (int d = 0; d < 64; d++) {
            const float qd = qs[g][d];
            o   = fmaf(qd, kvs[d][lane], o);
            nrm = fmaf(qd, kss[d], nrm);
        }
        attn[base + (size_t)t * D_ + lane] = o / fmaxf(nrm, 1e-6f);
        __syncthreads();
    }
}

// ---------------------------------------------------------------------------
// Launch
// ---------------------------------------------------------------------------
extern "C" void kernel_launch(void* const* d_in, const int* in_sizes, int n_in,
                              void* d_out, int out_size)
{
    (void)in_sizes; (void)n_in; (void)out_size;
    const float* x    = (const float*)d_in[0];
    const int*   mask = (const int*)d_in[1];     // bool marshaled as int32
    const float* Wq   = (const float*)d_in[2];
    const float* Wk   = (const float*)d_in[3];
    const float* Wv   = (const float*)d_in[4];
    const float* Wo   = (const float*)d_in[5];
    float* out = (float*)d_out;

    float *q, *k, *v, *kv, *ksum;
    cudaGetSymbolAddress((void**)&q,    g_q);
    cudaGetSymbolAddress((void**)&k,    g_k);
    cudaGetSymbolAddress((void**)&v,    g_v);
    cudaGetSymbolAddress((void**)&kv,   g_kv);
    cudaGetSymbolAddress((void**)&ksum, g_ksum);
    float* attn = k;   // alias: k is dead after kv_reduce

    dim3 gemm_grid(BT_ / 128, D_ / 128);   // 128 x 8

    // Projections with fused epilogues: q = phi, k = phi+mask, v = mask
    gemm_kernel<<<gemm_grid, 256>>>(x, Wq, q, nullptr, 1);
    gemm_kernel<<<gemm_grid, 256>>>(x, Wk, k, mask,   3);
    gemm_kernel<<<gemm_grid, 256>>>(x, Wv, v, mask,   2);

    // kv / ksum pooling over T
    kv_reduce<<<dim3(BH_, 4), 256>>>(k, v, kv, ksum);

    // q @ kv, normalized (writes into k buffer)
    attn_apply<<<dim3(BH_, T_ / 128), 256>>>(q, kv, ksum, attn);

    // Output projection
    gemm_kernel<<<gemm_grid, 256>>>(attn, Wo, out, nullptr, 0);
}

// round 6
// speedup vs baseline: 2.4778x; 2.4778x over previous
#include <cuda_runtime.h>
#include <cuda_bf16.h>
#include <cstdint>
#include <cstddef>

// Problem constants
#define B_  4
#define T_  4096
#define D_  1024
#define H_  16
#define HD_ 64
#define BT_ (B_ * T_)          // 16384 rows
#define BH_ (B_ * H_)          // 64 (b,h) pairs
#define KCH 8                  // T-chunks for kv reduction

// ---------------------------------------------------------------------------
// Scratch (device globals; attn aliases g_k which is dead after kv pooling)
// ---------------------------------------------------------------------------
__device__ float g_q[(size_t)BT_ * D_];
__device__ float g_k[(size_t)BT_ * D_];
__device__ float g_v[(size_t)BT_ * D_];
__device__ float g_kvp[(size_t)KCH * BH_ * HD_ * HD_];   // partial kv (8 MB)
__device__ float g_ksump[(size_t)KCH * BH_ * HD_];
__device__ float g_kv[(size_t)BH_ * HD_ * HD_];
__device__ float g_ksum[(size_t)BH_ * HD_];

__device__ __forceinline__ float phi_fn(float x) {
    return x > 0.f ? x + 1.f : __expf(x);
}

__device__ __forceinline__ uint32_t f2tf32(float x) {
    uint32_t r;
    asm("cvt.rna.tf32.f32 %0, %1;" : "=r"(r) : "f"(x));
    return r;
}

__device__ __forceinline__ void mma_tf32(float* c, const uint32_t* a, const uint32_t* b) {
    asm volatile(
        "mma.sync.aligned.m16n8k8.row.col.f32.tf32.tf32.f32 "
        "{%0,%1,%2,%3}, {%4,%5,%6,%7}, {%8,%9}, {%0,%1,%2,%3};\n"
        : "+f"(c[0]), "+f"(c[1]), "+f"(c[2]), "+f"(c[3])
        : "r"(a[0]), "r"(a[1]), "r"(a[2]), "r"(a[3]), "r"(b[0]), "r"(b[1]));
}

// ---------------------------------------------------------------------------
// tf32 tensor-core GEMM: C[row,col] = sum_k A[row,k] * W[col,k]
// A: M x K row-major, W: N x K row-major. M=16384, N=K=1024.
// Block tile 128x128, BK=16, double-buffered. 8 warps, warp tile 32x64.
// mode bit0 = phi epilogue, bit1 = zero masked rows (mask int32, AFTER phi).
// ---------------------------------------------------------------------------
__global__ __launch_bounds__(256, 2) void gemm_tf32(
    const float* __restrict__ A,
    const float* __restrict__ W,
    float* __restrict__ C,
    const int* __restrict__ mask,
    int mode)
{
    const int K = D_;
    const int N = D_;
    __shared__ uint32_t As[2][16][132];
    __shared__ uint32_t Bs[2][16][132];

    const int tid  = threadIdx.x;
    const int wid  = tid >> 5;
    const int lane = tid & 31;
    const int gid  = lane >> 2;   // 0..7
    const int tig  = lane & 3;    // 0..3
    const int warpM = wid & 3;    // 0..3 -> 32 rows each
    const int warpN = wid >> 2;   // 0..1 -> 64 cols each

    const int rowBase = blockIdx.x * 128;
    const int colBase = blockIdx.y * 128;

    const int lrow = tid >> 1;           // 0..127
    const int lkq  = (tid & 1) * 8;      // 0 or 8

    float acc[2][8][4];
    #pragma unroll
    for (int mt = 0; mt < 2; mt++)
        #pragma unroll
        for (int nt = 0; nt < 8; nt++)
            #pragma unroll
            for (int i = 0; i < 4; i++)
                acc[mt][nt][i] = 0.f;

    const float* Ap = A + (size_t)(rowBase + lrow) * K + lkq;
    const float* Wp = W + (size_t)(colBase + lrow) * K + lkq;

    float ag[8], bg[8];
    // preload chunk 0
    {
        float4 a0 = *(const float4*)(Ap + 0);
        float4 a1 = *(const float4*)(Ap + 4);
        float4 b0 = *(const float4*)(Wp + 0);
        float4 b1 = *(const float4*)(Wp + 4);
        ag[0]=a0.x; ag[1]=a0.y; ag[2]=a0.z; ag[3]=a0.w;
        ag[4]=a1.x; ag[5]=a1.y; ag[6]=a1.z; ag[7]=a1.w;
        bg[0]=b0.x; bg[1]=b0.y; bg[2]=b0.z; bg[3]=b0.w;
        bg[4]=b1.x; bg[5]=b1.y; bg[6]=b1.z; bg[7]=b1.w;
        #pragma unroll
        for (int j = 0; j < 8; j++) {
            As[0][lkq + j][lrow] = f2tf32(ag[j]);
            Bs[0][lkq + j][lrow] = f2tf32(bg[j]);
        }
    }
    __syncthreads();

    int buf = 0;
    for (int kb = 16; kb < K + 16; kb += 16) {
        const bool has_next = (kb < K);
        if (has_next) {
            float4 a0 = *(const float4*)(Ap + kb + 0);
            float4 a1 = *(const float4*)(Ap + kb + 4);
            float4 b0 = *(const float4*)(Wp + kb + 0);
            float4 b1 = *(const float4*)(Wp + kb + 4);
            ag[0]=a0.x; ag[1]=a0.y; ag[2]=a0.z; ag[3]=a0.w;
            ag[4]=a1.x; ag[5]=a1.y; ag[6]=a1.z; ag[7]=a1.w;
            bg[0]=b0.x; bg[1]=b0.y; bg[2]=b0.z; bg[3]=b0.w;
            bg[4]=b1.x; bg[5]=b1.y; bg[6]=b1.z; bg[7]=b1.w;
        }

        // compute on current buffer
        #pragma unroll
        for (int ks = 0; ks < 16; ks += 8) {
            uint32_t af[2][4];
            #pragma unroll
            for (int mt = 0; mt < 2; mt++) {
                const int m0 = warpM * 32 + mt * 16;
                af[mt][0] = As[buf][ks + tig    ][m0 + gid    ];
                af[mt][1] = As[buf][ks + tig    ][m0 + gid + 8];
                af[mt][2] = As[buf][ks + tig + 4][m0 + gid    ];
                af[mt][3] = As[buf][ks + tig + 4][m0 + gid + 8];
            }
            uint32_t bf[8][2];
            #pragma unroll
            for (int nt = 0; nt < 8; nt++) {
                const int n0 = warpN * 64 + nt * 8;
                bf[nt][0] = Bs[buf][ks + tig    ][n0 + gid];
                bf[nt][1] = Bs[buf][ks + tig + 4][n0 + gid];
            }
            #pragma unroll
            for (int mt = 0; mt < 2; mt++)
                #pragma unroll
                for (int nt = 0; nt < 8; nt++)
                    mma_tf32(acc[mt][nt], af[mt], bf[nt]);
        }

        if (has_next) {
            #pragma unroll
            for (int j = 0; j < 8; j++) {
                As[buf ^ 1][lkq + j][lrow] = f2tf32(ag[j]);
                Bs[buf ^ 1][lkq + j][lrow] = f2tf32(bg[j]);
            }
        }
        __syncthreads();
        buf ^= 1;
    }

    // Epilogue
    const bool do_phi  = (mode & 1) != 0;
    const bool do_mask = (mode & 2) != 0;

    #pragma unroll
    for (int mt = 0; mt < 2; mt++) {
        const int r0 = rowBase + warpM * 32 + mt * 16 + gid;
        const int r1 = r0 + 8;
        bool mz0 = false, mz1 = false;
        if (do_mask) { mz0 = (mask[r0] != 0); mz1 = (mask[r1] != 0); }
        #pragma unroll
        for (int nt = 0; nt < 8; nt++) {
            const int c = colBase + warpN * 64 + nt * 8 + 2 * tig;
            float v00 = acc[mt][nt][0], v01 = acc[mt][nt][1];
            float v10 = acc[mt][nt][2], v11 = acc[mt][nt][3];
            if (do_phi) { v00 = phi_fn(v00); v01 = phi_fn(v01);
                          v10 = phi_fn(v10); v11 = phi_fn(v11); }
            if (do_mask) {
                if (mz0) { v00 = 0.f; v01 = 0.f; }
                if (mz1) { v10 = 0.f; v11 = 0.f; }
            }
            *(float2*)(C + (size_t)r0 * N + c) = make_float2(v00, v01);
            *(float2*)(C + (size_t)r1 * N + c) = make_float2(v10, v11);
        }
    }
}

// ---------------------------------------------------------------------------
// kv pooling, T split into KCH chunks for parallelism.
// grid (BH, 4, KCH): block does 64 d x 16 e over 512 t.
// ---------------------------------------------------------------------------
__global__ __launch_bounds__(256) void kv_reduce_part(
    const float* __restrict__ k,
    const float* __restrict__ v,
    float* __restrict__ kvp,
    float* __restrict__ ksump)
{
    const int bh = blockIdx.x;
    const int jt = blockIdx.y;
    const int ch = blockIdx.z;
    const int b  = bh >> 4;
    const int h  = bh & 15;
    const int jbase = jt * 16;
    const int tstart = ch * (T_ / KCH);

    __shared__ float ks[64][64];
    __shared__ float vs[64][16];

    const int tid = threadIdx.x;
    const int i   = tid & 63;
    const int jj0 = (tid >> 6) * 4;

    float acc0 = 0.f, acc1 = 0.f, acc2 = 0.f, acc3 = 0.f, ksacc = 0.f;
    const size_t base = ((size_t)b * T_) * D_ + h * HD_;

    for (int t0 = tstart; t0 < tstart + T_ / KCH; t0 += 64) {
        #pragma unroll
        for (int r = 0; r < 16; r++) {
            int idx = r * 256 + tid;
            int tl = idx >> 6, ii = idx & 63;
            ks[tl][ii] = k[base + (size_t)(t0 + tl) * D_ + ii];
        }
        #pragma unroll
        for (int r = 0; r < 4; r++) {
            int idx = r * 256 + tid;
            int tl = idx >> 4, jj = idx & 15;
            vs[tl][jj] = v[base + (size_t)(t0 + tl) * D_ + jbase + jj];
        }
        __syncthreads();

        #pragma unroll 8
        for (int tl = 0; tl < 64; tl++) {
            float kk = ks[tl][i];
            ksacc += kk;
            acc0 = fmaf(kk, vs[tl][jj0 + 0], acc0);
            acc1 = fmaf(kk, vs[tl][jj0 + 1], acc1);
            acc2 = fmaf(kk, vs[tl][jj0 + 2], acc2);
            acc3 = fmaf(kk, vs[tl][jj0 + 3], acc3);
        }
        __syncthreads();
    }

    float* kvb = kvp + ((size_t)ch * BH_ + bh) * HD_ * HD_;
    kvb[i * HD_ + jbase + jj0 + 0] = acc0;
    kvb[i * HD_ + jbase + jj0 + 1] = acc1;
    kvb[i * HD_ + jbase + jj0 + 2] = acc2;
    kvb[i * HD_ + jbase + jj0 + 3] = acc3;
    if (jt == 0 && tid < 64)
        ksump[((size_t)ch * BH_ + bh) * HD_ + tid] = ksacc;
}

__global__ void kv_finalize(const float* __restrict__ kvp, float* __restrict__ kv)
{
    const int idx = blockIdx.x * 256 + threadIdx.x;   // 64*64*64 = 262144
    float s = 0.f;
    #pragma unroll
    for (int c = 0; c < KCH; c++)
        s += kvp[(size_t)c * (BH_ * HD_ * HD_) + idx];
    kv[idx] = s;
}

__global__ void ksum_finalize(const float* __restrict__ ksump, float* __restrict__ ksum)
{
    const int idx = blockIdx.x * 256 + threadIdx.x;   // 64*64 = 4096
    float s = 0.f;
    #pragma unroll
    for (int c = 0; c < KCH; c++)
        s += ksump[(size_t)c * (BH_ * HD_) + idx];
    ksum[idx] = s;
}

// ---------------------------------------------------------------------------
// apply: warp-per-row, no intra-loop block syncs.
// grid (BH, 16), block 256 = 8 warps; each warp does 32 t's.
// ---------------------------------------------------------------------------
__global__ __launch_bounds__(256) void attn_apply(
    const float* __restrict__ q,
    const float* __restrict__ kv,
    const float* __restrict__ ksum,
    float* __restrict__ attn)
{
    const int bh = blockIdx.x;
    const int b  = bh >> 4;
    const int h  = bh & 15;

    __shared__ float kvs[64][66];
    __shared__ float kss[64];

    const int tid = threadIdx.x;
    const float* kvb = kv + (size_t)bh * HD_ * HD_;
    #pragma unroll
    for (int r = 0; r < 16; r++) {
        int idx = r * 256 + tid;
        kvs[idx >> 6][idx & 63] = kvb[idx];
    }
    if (tid < 64) kss[tid] = ksum[bh * HD_ + tid];
    __syncthreads();

    const int wid  = tid >> 5;
    const int lane = tid & 31;
    const size_t base = ((size_t)b * T_) * D_ + h * HD_;

    for (int it = 0; it < 32; it++) {
        const int t = blockIdx.y * 256 + wid * 32 + it;
        const float* qr = q + base + (size_t)t * D_;
        const float2 qv = *(const float2*)(qr + 2 * lane);

        float o0 = 0.f, o1 = 0.f, nrm = 0.f;
        #pragma unroll
        for (int d = 0; d < 64; d++) {
            const float src = (d & 1) ? qv.y : qv.x;
            const float qd = __shfl_sync(0xffffffffu, src, d >> 1);
            o0  = fmaf(qd, kvs[d][2 * lane    ], o0);
            o1  = fmaf(qd, kvs[d][2 * lane + 1], o1);
            nrm = fmaf(qd, kss[d], nrm);
        }
        const float inv = 1.f / fmaxf(nrm, 1e-6f);
        *(float2*)(attn + base + (size_t)t * D_ + 2 * lane) = make_float2(o0 * inv, o1 * inv);
    }
}

// ---------------------------------------------------------------------------
// Launch
// ---------------------------------------------------------------------------
extern "C" void kernel_launch(void* const* d_in, const int* in_sizes, int n_in,
                              void* d_out, int out_size)
{
    (void)in_sizes; (void)n_in; (void)out_size;
    const float* x    = (const float*)d_in[0];
    const int*   mask = (const int*)d_in[1];     // bool marshaled as int32
    const float* Wq   = (const float*)d_in[2];
    const float* Wk   = (const float*)d_in[3];
    const float* Wv   = (const float*)d_in[4];
    const float* Wo   = (const float*)d_in[5];
    float* out = (float*)d_out;

    float *q, *k, *v, *kvp, *ksump, *kv, *ksum;
    cudaGetSymbolAddress((void**)&q,     g_q);
    cudaGetSymbolAddress((void**)&k,     g_k);
    cudaGetSymbolAddress((void**)&v,     g_v);
    cudaGetSymbolAddress((void**)&kvp,   g_kvp);
    cudaGetSymbolAddress((void**)&ksump, g_ksump);
    cudaGetSymbolAddress((void**)&kv,    g_kv);
    cudaGetSymbolAddress((void**)&ksum,  g_ksum);
    float* attn = k;   // alias: k dead after kv pooling

    dim3 gemm_grid(BT_ / 128, D_ / 128);   // 128 x 8

    gemm_tf32<<<gemm_grid, 256>>>(x, Wq, q, nullptr, 1);
    gemm_tf32<<<gemm_grid, 256>>>(x, Wk, k, mask,   3);
    gemm_tf32<<<gemm_grid, 256>>>(x, Wv, v, mask,   2);

    kv_reduce_part<<<dim3(BH_, 4, KCH), 256>>>(k, v, kvp, ksump);
    kv_finalize<<<(BH_ * HD_ * HD_) / 256, 256>>>(kvp, kv);
    ksum_finalize<<<(BH_ * HD_) / 256, 256>>>(ksump, ksum);

    attn_apply<<<dim3(BH_, T_ / 256), 256>>>(q, kv, ksum, attn);

    gemm_tf32<<<gemm_grid, 256>>>(attn, Wo, out, nullptr, 0);
}